// round 2
// baseline (speedup 1.0000x reference)
#include <cuda_runtime.h>

#define T_NO 200
#define SUB  16
#define E_NO 2000
#define I_NO 500
#define TD   20000
#define CB   16
#define CTL  128

// ---------------- scratch (static device globals; no allocation) -------------
__device__ float g_syn_e[TD * SUB];
__device__ float g_syn_i[TD * SUB];
__device__ float g_syn[TD * SUB];
__device__ int   g_asn_e[E_NO];
__device__ int   g_asn_i[I_NO];
__device__ float g_ek[SUB * T_NO];
__device__ float g_ik[SUB * T_NO];
__device__ float g_sk[SUB * T_NO];
__device__ float g_hk[SUB * T_NO];

// ---------------- kernel/filter precompute + neuron->subunit assignment -----
__global__ void k_prep(const float* __restrict__ C_syn_e,
                       const float* __restrict__ C_syn_i,
                       const float* __restrict__ Te, const float* __restrict__ Ti,
                       const float* __restrict__ We, const float* __restrict__ Wi,
                       const float* __restrict__ De, const float* __restrict__ Di,
                       const float* __restrict__ Tspk, const float* __restrict__ Wspk,
                       const float* __restrict__ Whist,
                       float* __restrict__ out_filt)
{
    int tid = threadIdx.x;
    for (int e = tid; e < E_NO; e += blockDim.x) {
        int a = 0;
        for (int s = 0; s < SUB; s++)
            if (C_syn_e[s * E_NO + e] > 0.5f) a = s;
        g_asn_e[e] = a;
    }
    for (int i = tid; i < I_NO; i += blockDim.x) {
        int a = 0;
        for (int s = 0; s < SUB; s++)
            if (C_syn_i[s * I_NO + i] > 0.5f) a = s;
        g_asn_i[i] = a;
    }
    const float PI = 3.14159265358979323846f;
    for (int idx = tid; idx < SUB * T_NO; idx += blockDim.x) {
        int s   = idx / T_NO;
        int tau = idx % T_NO;
        float t = (float)tau;

        float te  = fmaxf(t - expf(De[s]), 0.0f);
        float tte = te / expf(Te[s]);
        float ek  = tte * expf(-tte) * expf(We[s]);

        float ti_ = fmaxf(t - expf(Di[s]), 0.0f);
        float tti = ti_ / expf(Ti[s]);
        float ik  = -tti * expf(-tti) * expf(Wi[s]);

        float tts = t / expf(Tspk[s]);
        float sk  = tts * expf(-tts) * expf(Wspk[s]);

        float raw = 4.0f * logf(t + 1.0f);
        float hk  = 0.0f;
        for (int b = 0; b < CB; b++) {
            float phi = (PI * 0.5f) * (float)b;
            float v   = 0.5f * cosf(raw - phi) + 0.5f;
            if (raw < phi - PI || raw > phi + PI) v = 0.0f;
            hk += Whist[s * CB + b] * v;
        }
        g_ek[idx] = ek; g_ik[idx] = ik; g_sk[idx] = sk; g_hk[idx] = hk;

        // out_filters = vstack([e_kern, i_kern, spk_kern, hist_kern]) (64 x 200)
        out_filt[(s)      * T_NO + tau] = ek;
        out_filt[(16 + s) * T_NO + tau] = ik;
        out_filt[(32 + s) * T_NO + tau] = sk;
        out_filt[(48 + s) * T_NO + tau] = hk;
    }
}

// ---------------- one-hot pooling: exact integer counts ----------------------
__global__ void k_syn(const float* __restrict__ Se, const float* __restrict__ Si)
{
    __shared__ float be[SUB], bi[SUB];
    int t = blockIdx.x, tid = threadIdx.x;
    if (tid < SUB) { be[tid] = 0.0f; bi[tid] = 0.0f; }
    __syncthreads();
    for (int e = tid; e < E_NO; e += blockDim.x) {
        float v = Se[(size_t)t * E_NO + e];
        if (v != 0.0f) atomicAdd(&be[g_asn_e[e]], v);
    }
    for (int i = tid; i < I_NO; i += blockDim.x) {
        float v = Si[(size_t)t * I_NO + i];
        if (v != 0.0f) atomicAdd(&bi[g_asn_i[i]], v);
    }
    __syncthreads();
    if (tid < SUB) {
        g_syn_e[t * SUB + tid] = be[tid];
        g_syn_i[t * SUB + tid] = bi[tid];
    }
}

// ---------------- causal 200-tap depthwise conv ------------------------------
__global__ void k_conv()
{
    // kernels in smem, padded to 201 floats/row for conflict-free access
    __shared__ float sek[SUB * 201];
    __shared__ float sik[SUB * 201];
    int tid = threadIdx.x;
    for (int idx = tid; idx < SUB * T_NO; idx += blockDim.x) {
        int s = idx / T_NO, d = idx % T_NO;
        sek[s * 201 + d] = g_ek[idx];
        sik[s * 201 + d] = g_ik[idx];
    }
    __syncthreads();

    int t0  = blockIdx.x * CTL;
    int s   = tid & 15;
    int tl0 = tid >> 4;                 // 0..15
    for (int j = 0; j < CTL / 16; j++) {
        int t = t0 + tl0 + j * 16;
        if (t < TD) {
            float acc = 0.0f;
            const float* ke = &sek[s * 201];
            const float* ki = &sik[s * 201];
            #pragma unroll 4
            for (int d = 1; d <= T_NO; d++) {
                int u = t - d;
                float ve = (u >= 0) ? __ldg(&g_syn_e[u * SUB + s]) : 0.0f;
                float vi = (u >= 0) ? __ldg(&g_syn_i[u * SUB + s]) : 0.0f;
                acc += ve * ke[d - 1] + vi * ki[d - 1];
            }
            g_syn[t * SUB + s] = acc;
        }
    }
}

// ---------------- the sequential threshold scan (critical path) --------------
__global__ void __launch_bounds__(512, 1)
k_scan(const float* __restrict__ C_den, const float* __restrict__ Theta,
       float* __restrict__ out)
{
    __shared__ float buf[SUB][256];     // spike ring buffer, buf[s][time & 255]
    __shared__ float s_hsum[SUB];
    __shared__ float s_spkraw[SUB];

    int tid = threadIdx.x, wid = tid >> 5, lane = tid & 31;
    int s = wid;                         // warp w owns subunit w

    for (int i = tid; i < SUB * 256; i += blockDim.x)
        ((float*)buf)[i] = 0.0f;

    // per-lane fixed kernel weights: lags d = 1 + lane + 32k
    float wh[7], ws[7];
    #pragma unroll
    for (int k = 0; k < 7; k++) {
        int d = 1 + lane + 32 * k;
        bool v = (d <= T_NO);
        wh[k] = v ? g_hk[s * T_NO + d - 1] : 0.0f;
        ws[k] = v ? g_sk[s * T_NO + d - 1] : 0.0f;
    }

    float cden[16];
    float theta = 0.0f, syn_next = 0.0f;
    if (wid == 0 && lane < SUB) {
        #pragma unroll
        for (int k = 0; k < 16; k++) cden[k] = C_den[lane * SUB + k];
        theta    = Theta[lane];
        syn_next = g_syn[lane];          // syn[0, lane]
    }
    __syncthreads();

    for (int t = 0; t < TD; t++) {
        // stage 1: per-subunit history dot products (hist & spk share the load)
        int base = (t - 1 - lane) & 255;
        float h = 0.0f, p = 0.0f;
        #pragma unroll
        for (int k = 0; k < 7; k++) {
            float b = buf[s][(base - 32 * k) & 255];
            h += b * wh[k];
            p += b * ws[k];
        }
        #pragma unroll
        for (int off = 16; off >= 1; off >>= 1) {
            h += __shfl_xor_sync(0xffffffffu, h, off);
            p += __shfl_xor_sync(0xffffffffu, p, off);
        }
        if (lane == 0) { s_hsum[s] = h; s_spkraw[s] = p; }
        __syncthreads();

        // stage 2: C_den mix, threshold, ring/output write (warp 0)
        if (wid == 0 && lane < SUB) {
            float synv = syn_next;
            if (t + 1 < TD) syn_next = __ldg(&g_syn[(t + 1) * SUB + lane]); // prefetch
            float acc = s_hsum[lane] + synv + theta;
            #pragma unroll
            for (int k = 0; k < 16; k++) acc += cden[k] * s_spkraw[k];
            float sp = (acc > 0.0f) ? 1.0f : 0.0f;
            buf[lane][t & 255] = sp;
            out[t * SUB + lane] = sp;
        }
        __syncthreads();
    }
}

// ---------------- launcher ---------------------------------------------------
extern "C" void kernel_launch(void* const* d_in, const int* in_sizes, int n_in,
                              void* d_out, int out_size)
{
    const float* S_e     = (const float*)d_in[0];
    const float* S_i     = (const float*)d_in[1];
    const float* C_den   = (const float*)d_in[2];
    const float* C_syn_e = (const float*)d_in[3];
    const float* C_syn_i = (const float*)d_in[4];
    const float* Tau_e   = (const float*)d_in[5];
    const float* Tau_i   = (const float*)d_in[6];
    const float* W_e     = (const float*)d_in[7];
    const float* W_i     = (const float*)d_in[8];
    const float* D_e     = (const float*)d_in[9];
    const float* D_i     = (const float*)d_in[10];
    const float* Tau_spk = (const float*)d_in[11];
    const float* W_spk   = (const float*)d_in[12];
    const float* W_hist  = (const float*)d_in[13];
    const float* Theta   = (const float*)d_in[14];
    float* out = (float*)d_out;

    k_prep<<<1, 256>>>(C_syn_e, C_syn_i, Tau_e, Tau_i, W_e, W_i, D_e, D_i,
                       Tau_spk, W_spk, W_hist, out + (size_t)TD * SUB);
    k_syn<<<TD, 128>>>(S_e, S_i);
    k_conv<<<(TD + CTL - 1) / CTL, 256>>>();
    k_scan<<<1, 512>>>(C_den, Theta, out);
}

// round 3
// speedup vs baseline: 1.1318x; 1.1318x over previous
#include <cuda_runtime.h>

#define T_NO 200
#define SUB  16
#define E_NO 2000
#define I_NO 500
#define TD   20000
#define CB   16
#define CTL  128

// ---------------- scratch (static device globals; no allocation) -------------
__device__ float g_syn_e[TD * SUB];
__device__ float g_syn_i[TD * SUB];
__device__ float g_syn[TD * SUB];
__device__ int   g_asn_e[E_NO];
__device__ int   g_asn_i[I_NO];
__device__ float g_ek[SUB * T_NO];
__device__ float g_ik[SUB * T_NO];
__device__ float g_sk[SUB * T_NO];
__device__ float g_hk[SUB * T_NO];

// ---------------- kernel/filter precompute + neuron->subunit assignment -----
__global__ void k_prep(const float* __restrict__ C_syn_e,
                       const float* __restrict__ C_syn_i,
                       const float* __restrict__ Te, const float* __restrict__ Ti,
                       const float* __restrict__ We, const float* __restrict__ Wi,
                       const float* __restrict__ De, const float* __restrict__ Di,
                       const float* __restrict__ Tspk, const float* __restrict__ Wspk,
                       const float* __restrict__ Whist,
                       float* __restrict__ out_filt)
{
    int tid = threadIdx.x;
    for (int e = tid; e < E_NO; e += blockDim.x) {
        int a = 0;
        for (int s = 0; s < SUB; s++)
            if (C_syn_e[s * E_NO + e] > 0.5f) a = s;
        g_asn_e[e] = a;
    }
    for (int i = tid; i < I_NO; i += blockDim.x) {
        int a = 0;
        for (int s = 0; s < SUB; s++)
            if (C_syn_i[s * I_NO + i] > 0.5f) a = s;
        g_asn_i[i] = a;
    }
    const float PI = 3.14159265358979323846f;
    for (int idx = tid; idx < SUB * T_NO; idx += blockDim.x) {
        int s   = idx / T_NO;
        int tau = idx % T_NO;
        float t = (float)tau;

        float te  = fmaxf(t - expf(De[s]), 0.0f);
        float tte = te / expf(Te[s]);
        float ek  = tte * expf(-tte) * expf(We[s]);

        float ti_ = fmaxf(t - expf(Di[s]), 0.0f);
        float tti = ti_ / expf(Ti[s]);
        float ik  = -tti * expf(-tti) * expf(Wi[s]);

        float tts = t / expf(Tspk[s]);
        float sk  = tts * expf(-tts) * expf(Wspk[s]);

        float raw = 4.0f * logf(t + 1.0f);
        float hk  = 0.0f;
        for (int b = 0; b < CB; b++) {
            float phi = (PI * 0.5f) * (float)b;
            float v   = 0.5f * cosf(raw - phi) + 0.5f;
            if (raw < phi - PI || raw > phi + PI) v = 0.0f;
            hk += Whist[s * CB + b] * v;
        }
        g_ek[idx] = ek; g_ik[idx] = ik; g_sk[idx] = sk; g_hk[idx] = hk;

        out_filt[(s)      * T_NO + tau] = ek;
        out_filt[(16 + s) * T_NO + tau] = ik;
        out_filt[(32 + s) * T_NO + tau] = sk;
        out_filt[(48 + s) * T_NO + tau] = hk;
    }
}

// ---------------- one-hot pooling: exact integer counts ----------------------
__global__ void k_syn(const float* __restrict__ Se, const float* __restrict__ Si)
{
    __shared__ float be[SUB], bi[SUB];
    int t = blockIdx.x, tid = threadIdx.x;
    if (tid < SUB) { be[tid] = 0.0f; bi[tid] = 0.0f; }
    __syncthreads();
    for (int e = tid; e < E_NO; e += blockDim.x) {
        float v = Se[(size_t)t * E_NO + e];
        if (v != 0.0f) atomicAdd(&be[g_asn_e[e]], v);
    }
    for (int i = tid; i < I_NO; i += blockDim.x) {
        float v = Si[(size_t)t * I_NO + i];
        if (v != 0.0f) atomicAdd(&bi[g_asn_i[i]], v);
    }
    __syncthreads();
    if (tid < SUB) {
        g_syn_e[t * SUB + tid] = be[tid];
        g_syn_i[t * SUB + tid] = bi[tid];
    }
}

// ---------------- causal 200-tap depthwise conv ------------------------------
__global__ void k_conv()
{
    __shared__ float sek[SUB * 201];
    __shared__ float sik[SUB * 201];
    int tid = threadIdx.x;
    for (int idx = tid; idx < SUB * T_NO; idx += blockDim.x) {
        int s = idx / T_NO, d = idx % T_NO;
        sek[s * 201 + d] = g_ek[idx];
        sik[s * 201 + d] = g_ik[idx];
    }
    __syncthreads();

    int t0  = blockIdx.x * CTL;
    int s   = tid & 15;
    int tl0 = tid >> 4;
    for (int j = 0; j < CTL / 16; j++) {
        int t = t0 + tl0 + j * 16;
        if (t < TD) {
            float acc = 0.0f;
            const float* ke = &sek[s * 201];
            const float* ki = &sik[s * 201];
            #pragma unroll 4
            for (int d = 1; d <= T_NO; d++) {
                int u = t - d;
                float ve = (u >= 0) ? __ldg(&g_syn_e[u * SUB + s]) : 0.0f;
                float vi = (u >= 0) ? __ldg(&g_syn_i[u * SUB + s]) : 0.0f;
                acc += ve * ke[d - 1] + vi * ki[d - 1];
            }
            g_syn[t * SUB + s] = acc;
        }
    }
}

// ---------------- the sequential threshold scan (critical path) --------------
// 16 warps, warp w owns subunit w. Warp-private duplicated spike ring (512
// floats: entry at p and p+256) => tap loads are LDS [base + const-imm], no
// per-tap modulo. Lanes 0-15 accumulate hist taps, lanes 16-31 spk taps
// (13 taps/lane, d = 1 + (lane&15) + 16k). ONE depth-4 butterfly reduces both
// halves simultaneously. p published to parity-double-buffered smem row; ONE
// __syncthreads per step; then lane 0 of each warp does its own C_den dot +
// threshold + ring/out write (ring is warp-private -> no second barrier).
__global__ void __launch_bounds__(512, 1)
k_scan(const float* __restrict__ C_den, const float* __restrict__ Theta,
       float* __restrict__ out)
{
    __shared__ float ring[SUB][512];
    __shared__ __align__(16) float sp[2][SUB];

    int tid = threadIdx.x, wid = tid >> 5, lane = tid & 31;
    int l15 = lane & 15;
    int w = wid;

    for (int i = tid; i < SUB * 512; i += blockDim.x)
        ((float*)ring)[i] = 0.0f;

    // per-lane fixed weights: taps d = 1 + l15 + 16k, k = 0..12
    // lanes 0-15: hist kernel; lanes 16-31: spk kernel
    float wgt[13];
    {
        const float* kb = (lane < 16) ? &g_hk[w * T_NO] : &g_sk[w * T_NO];
        #pragma unroll
        for (int k = 0; k < 13; k++) {
            int d = 1 + l15 + 16 * k;
            wgt[k] = (d <= T_NO) ? kb[d - 1] : 0.0f;
        }
    }

    // lane 0 per warp: C_den row, theta, syn 2-deep prefetch pipeline
    float cden[16];
    float theta = 0.0f, syn0 = 0.0f, syn1 = 0.0f;
    if (lane == 0) {
        #pragma unroll
        for (int k = 0; k < 16; k++) cden[k] = C_den[w * SUB + k];
        theta = Theta[w];
        syn0  = __ldg(&g_syn[0 * SUB + w]);
        syn1  = __ldg(&g_syn[1 * SUB + w]);
    }
    __syncthreads();

    const float* myring = &ring[w][0];

    for (int t = 0; t < TD; t++) {
        // ----- stage 1: tap accumulation + single depth-4 butterfly ---------
        int base = 256 + ((t - 1 - l15) & 255);   // tap k at [base - 16k]
        float a0 = 0.0f, a1 = 0.0f;
        #pragma unroll
        for (int k = 0; k < 13; k += 2) {
            a0 += myring[base - 16 * k] * wgt[k];
            if (k + 1 < 13) a1 += myring[base - 16 * (k + 1)] * wgt[k + 1];
        }
        float v = a0 + a1;
        #pragma unroll
        for (int off = 8; off >= 1; off >>= 1)
            v += __shfl_xor_sync(0xffffffffu, v, off);
        // lanes 0-15 now hold h (hist sum), lanes 16-31 hold p (spk_raw)
        int par = t & 1;
        if (lane == 16) sp[par][w] = v;
        __syncthreads();

        // ----- stage 2: per-warp C_den mix + threshold + ring write ---------
        if (lane == 0) {
            const float4* p4 = (const float4*)&sp[par][0];
            float4 q0 = p4[0], q1 = p4[1], q2 = p4[2], q3 = p4[3];
            float b0 = cden[0]*q0.x + cden[4]*q1.x + cden[8]*q2.x  + cden[12]*q3.x;
            float b1 = cden[1]*q0.y + cden[5]*q1.y + cden[9]*q2.y  + cden[13]*q3.y;
            float b2 = cden[2]*q0.z + cden[6]*q1.z + cden[10]*q2.z + cden[14]*q3.z;
            float b3 = cden[3]*q0.w + cden[7]*q1.w + cden[11]*q2.w + cden[15]*q3.w;
            float acc = ((b0 + b1) + (b2 + b3)) + v + syn0 + theta;  // v == h here
            float spk = (acc > 0.0f) ? 1.0f : 0.0f;
            int p = t & 255;
            ring[w][p]       = spk;
            ring[w][p + 256] = spk;
            out[t * SUB + w] = spk;
            syn0 = syn1;
            if (t + 2 < TD) syn1 = __ldg(&g_syn[(t + 2) * SUB + w]);
        }
        // no second barrier: ring is warp-private; sp is parity double-buffered
    }
}

// ---------------- launcher ---------------------------------------------------
extern "C" void kernel_launch(void* const* d_in, const int* in_sizes, int n_in,
                              void* d_out, int out_size)
{
    const float* S_e     = (const float*)d_in[0];
    const float* S_i     = (const float*)d_in[1];
    const float* C_den   = (const float*)d_in[2];
    const float* C_syn_e = (const float*)d_in[3];
    const float* C_syn_i = (const float*)d_in[4];
    const float* Tau_e   = (const float*)d_in[5];
    const float* Tau_i   = (const float*)d_in[6];
    const float* W_e     = (const float*)d_in[7];
    const float* W_i     = (const float*)d_in[8];
    const float* D_e     = (const float*)d_in[9];
    const float* D_i     = (const float*)d_in[10];
    const float* Tau_spk = (const float*)d_in[11];
    const float* W_spk   = (const float*)d_in[12];
    const float* W_hist  = (const float*)d_in[13];
    const float* Theta   = (const float*)d_in[14];
    float* out = (float*)d_out;

    k_prep<<<1, 256>>>(C_syn_e, C_syn_i, Tau_e, Tau_i, W_e, W_i, D_e, D_i,
                       Tau_spk, W_spk, W_hist, out + (size_t)TD * SUB);
    k_syn<<<TD, 128>>>(S_e, S_i);
    k_conv<<<(TD + CTL - 1) / CTL, 256>>>();
    k_scan<<<1, 512>>>(C_den, Theta, out);
}